// round 16
// baseline (speedup 1.0000x reference)
#include <cuda_runtime.h>
#include <cstdint>

typedef unsigned long long u64;

#define B_SZ   8192
#define NPROD  50
#define DXF    32
#define DZF    20
#define NROWS  (B_SZ * NPROD)       // 409600
#define WP128  140                  // 128-wide weight pitch (floats), remapped
#define UAP    132                  // u-kernel A-tile pitch (128 rows)
#define XAP    132                  // x-kernel A/H pitch (128 rows)

// ---------------- scratch (device globals, no allocation) ----------------
__device__ float g_Zj[3 * B_SZ * 16];                    // [KZ][B][16]
__device__ float g_D[3 * B_SZ * 128];                    // [KZ][B][128]
__device__ float g_E[(size_t)3 * 128 * NROWS];           // [KX][128][NROWS] column-major
__device__ float g_scores[9 * NROWS];                    // [pair][B][n]

// ---------------- packed f32x2 helpers ----------------
__device__ __forceinline__ u64 pk2(float lo, float hi) {
    u64 r; asm("mov.b64 %0, {%1, %2};" : "=l"(r) : "f"(lo), "f"(hi)); return r;
}
__device__ __forceinline__ void upk2(u64 v, float& lo, float& hi) {
    asm("mov.b64 {%0, %1}, %2;" : "=f"(lo), "=f"(hi) : "l"(v));
}
__device__ __forceinline__ void f2fma(u64& d, u64 a, u64 b) {
    asm("fma.rn.f32x2 %0, %1, %2, %0;" : "+l"(d) : "l"(a), "l"(b));
}
// fast elu: MUFU-based exp; abs err ~1e-6, fine vs 1e-3 threshold
__device__ __forceinline__ float eluf(float x) { return x > 0.f ? x : (__expf(x) - 1.f); }

__device__ __forceinline__ uint32_t smem_u32(const void* p) {
    uint32_t a;
    asm("{ .reg .u64 t; cvta.to.shared.u64 t, %1; cvt.u32.u64 %0, t; }" : "=r"(a) : "l"(p));
    return a;
}
__device__ __forceinline__ void cpasync16(uint32_t dst, const void* src) {
    asm volatile("cp.async.ca.shared.global [%0], [%1], 16;" :: "r"(dst), "l"(src) : "memory");
}
#define CP_COMMIT() asm volatile("cp.async.commit_group;" ::: "memory")
#define CP_WAIT(n)  asm volatile("cp.async.wait_group %0;" :: "n"(n) : "memory")

// Dense layer, register input/output, weights in shared. [IN][OUT] row-major.
template<int IN, int OUT, bool ELU>
__device__ __forceinline__ void dense_reg(const float (&in)[IN], const float* wsh, float (&out)[OUT]) {
    u64 acc[OUT / 2];
#pragma unroll
    for (int jj = 0; jj < OUT / 2; jj++) acc[jj] = 0ull;
#pragma unroll
    for (int k = 0; k < IN; k++) {
        u64 xk = pk2(in[k], in[k]);
        const ulonglong2* w = (const ulonglong2*)(wsh + k * OUT);
#pragma unroll
        for (int q = 0; q < OUT / 4; q++) {
            ulonglong2 ww = w[q];
            f2fma(acc[2 * q],     xk, ww.x);
            f2fma(acc[2 * q + 1], xk, ww.y);
        }
    }
#pragma unroll
    for (int jj = 0; jj < OUT / 2; jj++) {
        float lo, hi; upk2(acc[jj], lo, hi);
        out[2 * jj]     = ELU ? eluf(lo) : lo;
        out[2 * jj + 1] = ELU ? eluf(hi) : hi;
    }
}

template<int IN>
__device__ __forceinline__ void dense_half_reg(const float (&in)[IN], const float* wcol, u64 (&acc)[32]) {
#pragma unroll
    for (int q = 0; q < 32; q++) acc[q] = 0ull;
#pragma unroll
    for (int k = 0; k < IN; k++) {
        u64 uk = pk2(in[k], in[k]);
        const ulonglong2* w = (const ulonglong2*)(wcol + k * 128);
#pragma unroll
        for (int q = 0; q < 16; q++) {
            ulonglong2 ww = w[q];
            f2fma(acc[2 * q],     uk, ww.x);
            f2fma(acc[2 * q + 1], uk, ww.y);
        }
    }
}

// ============================================================
// Kernel 1: Z-branch.
// ============================================================
__global__ void __launch_bounds__(128) z_kernel(const float* __restrict__ Zin,
                                                const float* __restrict__ Wz0,
                                                const float* __restrict__ Wz,
                                                const float* __restrict__ Wlz) {
    __shared__ __align__(16) float w0[20 * 64];
    __shared__ __align__(16) float w1[64 * 64];
    __shared__ __align__(16) float w2[64 * 64];
    __shared__ __align__(16) float wl[64 * 16];
    const int j   = blockIdx.x >> 6;
    const int tid = threadIdx.x;
    const int b   = ((blockIdx.x & 63) << 7) + tid;

    {
        const float4* p0 = (const float4*)(Wz0 + j * 1280);
        const float4* p1 = (const float4*)(Wz  + j * 8192);
        const float4* p2 = (const float4*)(Wz  + j * 8192 + 4096);
        const float4* pl = (const float4*)(Wlz + j * 1024);
        for (int t = tid; t < 320;  t += 128) ((float4*)w0)[t] = p0[t];
        for (int t = tid; t < 1024; t += 128) ((float4*)w1)[t] = p1[t];
        for (int t = tid; t < 1024; t += 128) ((float4*)w2)[t] = p2[t];
        for (int t = tid; t < 256;  t += 128) ((float4*)wl)[t] = pl[t];
    }
    __syncthreads();

    float zv[20];
    const float4* zr = (const float4*)(Zin + (size_t)b * DZF);
#pragma unroll
    for (int t = 0; t < 5; t++) {
        float4 v = zr[t];
        zv[4 * t] = v.x; zv[4 * t + 1] = v.y; zv[4 * t + 2] = v.z; zv[4 * t + 3] = v.w;
    }

    float h1[64], h2[64], o[16];
    dense_reg<20, 64, true >(zv, w0, h1);
    dense_reg<64, 64, true >(h1, w1, h2);
    dense_reg<64, 64, true >(h2, w2, h1);
    dense_reg<64, 16, false>(h1, wl, o);

    float4* dst = (float4*)(g_Zj + (size_t)(j * B_SZ + b) * 16);
#pragma unroll
    for (int t = 0; t < 4; t++)
        dst[t] = make_float4(o[4 * t], o[4 * t + 1], o[4 * t + 2], o[4 * t + 3]);
}

// ============================================================
// Kernel 2: D_j[b][:] = Zj_j[b]·Wu0[48:64] + Z[b]·Wu0[64:84]
// ============================================================
__global__ void __launch_bounds__(256) d_kernel(const float* __restrict__ Zin,
                                                const float* __restrict__ Wu0) {
    __shared__ __align__(16) float w[36 * 128];
    const int j   = blockIdx.y;
    const int tid = threadIdx.x;
    const int b   = blockIdx.x * 256 + tid;

    const float4* src = (const float4*)(Wu0 + 48 * 128);
    for (int t = tid; t < 36 * 32; t += 256) ((float4*)w)[t] = src[t];
    __syncthreads();

    float in[36];
    const float4* zj = (const float4*)(g_Zj + (size_t)(j * B_SZ + b) * 16);
#pragma unroll
    for (int t = 0; t < 4; t++) {
        float4 v = zj[t];
        in[4 * t] = v.x; in[4 * t + 1] = v.y; in[4 * t + 2] = v.z; in[4 * t + 3] = v.w;
    }
    const float4* zr = (const float4*)(Zin + (size_t)b * DZF);
#pragma unroll
    for (int t = 0; t < 5; t++) {
        float4 v = zr[t];
        in[16 + 4 * t] = v.x; in[17 + 4 * t] = v.y; in[18 + 4 * t] = v.z; in[19 + 4 * t] = v.w;
    }

    float* dst = g_D + (size_t)(j * B_SZ + b) * 128;
    u64 acc[32];
#pragma unroll
    for (int half = 0; half < 2; half++) {
        dense_half_reg<36>(in, w + half * 64, acc);
        float4* d4 = (float4*)(dst + half * 64);
#pragma unroll
        for (int q = 0; q < 16; q++) {
            float a, bb, c, d;
            upk2(acc[2 * q], a, bb); upk2(acc[2 * q + 1], c, d);
            d4[q] = make_float4(a, bb, c, d);
        }
    }
}

// ============================================================
// Shared-weight staging with bank-group remaps (NON-OVERLAPPING).
// W68 (64-wide, pitch 68): off(ch) = ch*8 + ((ch>>2)&1)*4
// W140 (128-wide, pitch 140): off(ch) = ch*16 + (ch>>1)*4
// ============================================================
__device__ __forceinline__ void stage64(float* W68, const float* __restrict__ Wg,
                                        int Krows, int tid, int nthr) {
    for (int t = tid; t < Krows * 16; t += nthr) {
        int k = t >> 4, c4 = t & 15, ch = c4 >> 1, wi = c4 & 1;
        ((float4*)W68)[k * 17 + ch * 2 + ((ch >> 2) & 1) + wi] = ((const float4*)Wg)[t];
    }
}
__device__ __forceinline__ void stage128(float* W140, const float* __restrict__ Wg,
                                         int Krows, int tid, int nthr) {
    for (int t = tid; t < Krows * 32; t += nthr) {
        int k = t >> 5, c4 = t & 31, ch = c4 >> 2, wi = c4 & 3;
        ((float4*)W140)[k * 35 + ch * 4 + (ch >> 1) + wi] = ((const float4*)Wg)[t];
    }
}
__device__ __forceinline__ int wcol128(int chunk) {    // float offset of chunk base
    return chunk * 16 + (chunk >> 1) * 4;
}
// async: 32-k chunk (1024 src float4), remapped, one commit group (256 thr)
__device__ __forceinline__ void stage32_async(uint32_t dstbase, const float* __restrict__ Wg,
                                              int tid) {
#pragma unroll
    for (int it = 0; it < 4; it++) {
        int t = tid + it * 256;
        int k = t >> 5, c4 = t & 31, ch = c4 >> 2, wi = c4 & 3;
        cpasync16(dstbase + (uint32_t)(k * 35 + ch * 4 + (ch >> 1) + wi) * 16u,
                  (const float4*)Wg + t);
    }
    CP_COMMIT();
}

// 128-row x 64-col tile GEMM; micro 4 rows x 8 cols (rows paired). 256 thr.
template<int K, bool ELU>
__device__ __forceinline__ void gemm_tile64(const float* Ain, const float* W68, float* Aout,
                                            int row4, int tn8) {
    u64 acc[16];
#pragma unroll
    for (int q = 0; q < 16; q++) acc[q] = 0ull;
    const int wb = tn8 * 8 + ((tn8 >> 2) & 1) * 4;
#pragma unroll 4
    for (int k = 0; k < K; k++) {
        ulonglong2 ap = *(const ulonglong2*)(Ain + k * XAP + row4);
        const float4* wp = (const float4*)(W68 + k * 68 + wb);
        float4 b0 = wp[0], b1 = wp[1];
        u64 bd[8];
        bd[0] = pk2(b0.x, b0.x); bd[1] = pk2(b0.y, b0.y);
        bd[2] = pk2(b0.z, b0.z); bd[3] = pk2(b0.w, b0.w);
        bd[4] = pk2(b1.x, b1.x); bd[5] = pk2(b1.y, b1.y);
        bd[6] = pk2(b1.z, b1.z); bd[7] = pk2(b1.w, b1.w);
#pragma unroll
        for (int c = 0; c < 8; c++) {
            f2fma(acc[c],     ap.x, bd[c]);
            f2fma(acc[8 + c], ap.y, bd[c]);
        }
    }
#pragma unroll
    for (int c = 0; c < 8; c++) {
        float l0, h0, l1, h1;
        upk2(acc[c], l0, h0); upk2(acc[8 + c], l1, h1);
        if (ELU) { l0 = eluf(l0); h0 = eluf(h0); l1 = eluf(l1); h1 = eluf(h1); }
        *(float4*)(Aout + (tn8 * 8 + c) * XAP + row4) = make_float4(l0, h0, l1, h1);
    }
}

// ============================================================
// Kernel 3: X-branch, 128-row tiles, 256 threads, 2 blocks/SM.
// ============================================================
#define XO_AX 0
#define XO_H  (32 * XAP)              // 4224
#define XO_W  (XO_H + 128 * XAP)      // 21120
#define X_SMEM_FLOATS (XO_W + 6720)   // 27840 floats = 111360 B

__global__ void __launch_bounds__(256, 2) x_kernel(const float* __restrict__ Xin,
                                                   const float* __restrict__ Wx0,
                                                   const float* __restrict__ Wx,
                                                   const float* __restrict__ Wlx,
                                                   const float* __restrict__ Wu0) {
    extern __shared__ float xs[];
    float* AX = xs + XO_AX;
    float* H  = xs + XO_H;            // h1 = H, h2/LX = H + 64*XAP
    float* Wq = xs + XO_W;

    const int i   = blockIdx.y;
    const int tid = threadIdx.x;
    const int r0  = blockIdx.x * 128;

    const int row4 = (tid >> 3) * 4;          // 0..124 (32 groups)
    const int tn8  = tid & 7;

    const int rowE   = (tid & 31) * 4;        // 0..124
    const int chunkE = tid >> 5;              // 0..7
    const int wcolE  = wcol128(chunkE);
    const int col_offE = chunkE * 16;

    for (int t = tid; t < 1024; t += 256) {
        int m = t & 127, q = t >> 7;
        float4 v = *(const float4*)(Xin + (size_t)(r0 + m) * DXF + q * 4);
        AX[(q * 4 + 0) * XAP + m] = v.x; AX[(q * 4 + 1) * XAP + m] = v.y;
        AX[(q * 4 + 2) * XAP + m] = v.z; AX[(q * 4 + 3) * XAP + m] = v.w;
    }
    stage64(Wq, Wx0 + i * 2048, 32, tid, 256);
    __syncthreads();

    gemm_tile64<32, true>(AX, Wq, H, row4, tn8);                  // L1 -> h1
    __syncthreads();
    stage64(Wq, Wx + i * 8192, 64, tid, 256);
    __syncthreads();
    gemm_tile64<64, true>(H, Wq, H + 64 * XAP, row4, tn8);        // L2 -> h2
    __syncthreads();
    stage64(Wq, Wx + i * 8192 + 4096, 64, tid, 256);
    __syncthreads();
    gemm_tile64<64, true>(H + 64 * XAP, Wq, H, row4, tn8);        // L3 -> h1
    __syncthreads();
    for (int t = tid; t < 256; t += 256) {
        int k = t >> 2, c4 = t & 3;
        ((float4*)Wq)[k * 5 + c4] = ((const float4*)(Wlx + 2 * 1024))[t];  // Wlx[DX-1] (ref bug)
    }
    __syncthreads();
    {
        u64 acc[4];
#pragma unroll
        for (int q = 0; q < 4; q++) acc[q] = 0ull;
#pragma unroll 4
        for (int k = 0; k < 64; k++) {
            ulonglong2 ap = *(const ulonglong2*)(H + k * XAP + row4);
            float2 bw = *(const float2*)(Wq + k * 20 + tn8 * 2);
            u64 b0 = pk2(bw.x, bw.x), b1 = pk2(bw.y, bw.y);
            f2fma(acc[0], ap.x, b0); f2fma(acc[1], ap.x, b1);
            f2fma(acc[2], ap.y, b0); f2fma(acc[3], ap.y, b1);
        }
#pragma unroll
        for (int cc = 0; cc < 2; cc++) {
            float l0, h0, l1, h1;
            upk2(acc[cc], l0, h0); upk2(acc[2 + cc], l1, h1);
            *(float4*)(H + (64 + tn8 * 2 + cc) * XAP + row4) = make_float4(l0, h0, l1, h1);
        }
    }
    __syncthreads();
    stage128(Wq, Wu0, 48, tid, 256);
    __syncthreads();

    u64 acc[32];
    {
#pragma unroll
        for (int q = 0; q < 32; q++) acc[q] = 0ull;
#pragma unroll 4
        for (int k = 0; k < 48; k++) {
            const float* Ain = (k < 32) ? (AX + k * XAP) : (H + (64 + k - 32) * XAP);
            float4 av = *(const float4*)(Ain + rowE);
            const ulonglong2* bp = (const ulonglong2*)(Wq + k * WP128 + wcolE);
            ulonglong2 q0 = bp[0], q1 = bp[1], q2 = bp[2], q3 = bp[3];
            u64 bv[8] = {q0.x, q0.y, q1.x, q1.y, q2.x, q2.y, q3.x, q3.y};
            u64 av2[4];
            av2[0] = pk2(av.x, av.x); av2[1] = pk2(av.y, av.y);
            av2[2] = pk2(av.z, av.z); av2[3] = pk2(av.w, av.w);
#pragma unroll
            for (int r = 0; r < 4; r++)
#pragma unroll
                for (int c2 = 0; c2 < 8; c2++)
                    f2fma(acc[r * 8 + c2], av2[r], bv[c2]);
        }
    }
    __syncthreads();   // all LE reads of AX/LX done before overwriting H

#pragma unroll
    for (int c2 = 0; c2 < 8; c2++) {
        float lo0, hi0, lo1, hi1, lo2, hi2, lo3, hi3;
        upk2(acc[0 * 8 + c2], lo0, hi0);
        upk2(acc[1 * 8 + c2], lo1, hi1);
        upk2(acc[2 * 8 + c2], lo2, hi2);
        upk2(acc[3 * 8 + c2], lo3, hi3);
        int col = col_offE + 2 * c2;
        *(float4*)(H + col * XAP + rowE)       = make_float4(lo0, lo1, lo2, lo3);
        *(float4*)(H + (col + 1) * XAP + rowE) = make_float4(hi0, hi1, hi2, hi3);
    }
    __syncthreads();

    for (int t = tid; t < 4096; t += 256) {
        int c = t >> 5, q = t & 31;
        float4 v = *(const float4*)(H + c * XAP + q * 4);
        *(float4*)(g_E + ((size_t)i * 128 + c) * NROWS + r0 + q * 4) = v;
    }
}

// ============================================================
// Kernel 4: U-kernel, 128x128 tile, 256 threads, 2 blocks/SM.
// Prefetch-distance-1 cp.async pipeline: ONE sync per chunk.
// ============================================================
#define U2_A   0                          // 128 x 132 = 16896 floats
#define U2_W0  16896                      // 32 x 140 = 4480
#define U2_W1  (U2_W0 + 32 * WP128)       // 21376
#define U2_D   (U2_W1 + 32 * WP128)       // 25856 (4 x 132 = 528)
#define U2_WL  (U2_D + 528)               // 26384
#define U_SMEM_FLOATS (U2_WL + 128)       // 26512 floats = 106048 B

__device__ __forceinline__ void u_chunk32(const float* __restrict__ A0,
                                          const float* __restrict__ Wb,
                                          int row_off, int wcol, u64* acc) {
#pragma unroll 8
    for (int kk = 0; kk < 32; kk++) {
        float4 av = *(const float4*)(A0 + kk * UAP + row_off);
        const ulonglong2* bp = (const ulonglong2*)(Wb + kk * WP128 + wcol);
        ulonglong2 q0 = bp[0], q1 = bp[1], q2 = bp[2], q3 = bp[3];
        u64 bv[8] = {q0.x, q0.y, q1.x, q1.y, q2.x, q2.y, q3.x, q3.y};
        u64 av2[4];
        av2[0] = pk2(av.x, av.x); av2[1] = pk2(av.y, av.y);
        av2[2] = pk2(av.z, av.z); av2[3] = pk2(av.w, av.w);
#pragma unroll
        for (int r = 0; r < 4; r++)
#pragma unroll
            for (int c2 = 0; c2 < 8; c2++)
                f2fma(acc[r * 8 + c2], av2[r], bv[c2]);
    }
}

__global__ void __launch_bounds__(256, 2) u_kernel(const float* __restrict__ Wu,
                                                   const float* __restrict__ Wlast) {
    extern __shared__ float sm[];
    float* Asm = sm + U2_A;
    float* Dsh = sm + U2_D;
    float* wl  = sm + U2_WL;
    const uint32_t w0u = smem_u32(sm + U2_W0);
    const uint32_t w1u = smem_u32(sm + U2_W1);

    const int tid  = threadIdx.x;
    const int bx   = blockIdx.x;             // 0..28799
    const int pair = bx / 3200;
    const int tile = bx - pair * 3200;
    const int r0   = tile * 128;
    const int i    = pair / 3;
    const int j    = pair - 3 * i;
    const int b0   = r0 / NPROD;

    const int wid    = tid >> 5;              // 0..7
    const int warp_c = wid & 1;
    const int warp_r = wid >> 1;               // 0..3
    const int lane   = tid & 31;
    const int lr     = lane & 7;
    const int lc     = lane >> 3;
    const int row_off = warp_r * 32 + lr * 4;   // 0..124
    const int chunk   = warp_c * 4 + lc;        // 0..7
    const int wcol    = wcol128(chunk);
    const int col_off = chunk * 16;

    // ---- prefetch chunk 0; stage D + wlast ----
    stage32_async(w0u, Wu, tid);                 // chunk 0 -> W0
    for (int t = tid; t < 512; t += 256) {
        int bl = t >> 7, k = t & 127;
        int bb = b0 + bl;
        if (bb < B_SZ) Dsh[bl * 132 + k] = g_D[((size_t)j * B_SZ + bb) * 128 + k];
    }
    if (tid < 128) wl[tid] = Wlast[tid];
    __syncthreads();   // Dsh visible

    // ---- prologue: A[k][m] = elu(E + D) (overlaps cp.async chunk 0) ----
    {
        const float* Eb = g_E + (size_t)i * 128 * NROWS + r0;
#pragma unroll 4
        for (int it = 0; it < 16; it++) {
            int v = tid + it * 256;
            int k = v >> 5;
            int m = (v & 31) * 4;
            float4 e = *(const float4*)(Eb + (size_t)k * NROWS + m);
            int rg = r0 + m;
            float o0 = eluf(e.x + Dsh[((rg    ) / NPROD - b0) * 132 + k]);
            float o1 = eluf(e.y + Dsh[((rg + 1) / NPROD - b0) * 132 + k]);
            float o2 = eluf(e.z + Dsh[((rg + 2) / NPROD - b0) * 132 + k]);
            float o3 = eluf(e.w + Dsh[((rg + 3) / NPROD - b0) * 132 + k]);
            *(float4*)(Asm + k * UAP + m) = make_float4(o0, o1, o2, o3);
        }
    }
    CP_WAIT(0);
    __syncthreads();   // A visible + chunk 0 ready

    u64 acc[32];
#pragma unroll
    for (int q = 0; q < 32; q++) acc[q] = 0ull;

    // ---- 8 chunks, prefetch distance 1, one sync per chunk ----
    // chunk s lives in buf (s&1); prefetch of s+1 targets the other buffer,
    // whose previous reader (chunk s-1) is past the sync at top of this iter.
#pragma unroll 1
    for (int s = 0; s < 8; s++) {
        if (s < 7) stage32_async((s & 1) ? w0u : w1u, Wu + (s + 1) * 4096, tid);
        u_chunk32(Asm + (s & 3) * 32 * UAP, sm + ((s & 1) ? U2_W1 : U2_W0),
                  row_off, wcol, acc);
        if (s == 3) {
            __syncthreads();   // all warps done reading A (layer-0 complete)
            // transition: A[col][m] = elu(out[m][col]); reset acc
#pragma unroll
            for (int c2 = 0; c2 < 8; c2++) {
                float lo0, hi0, lo1, hi1, lo2, hi2, lo3, hi3;
                upk2(acc[0 * 8 + c2], lo0, hi0);
                upk2(acc[1 * 8 + c2], lo1, hi1);
                upk2(acc[2 * 8 + c2], lo2, hi2);
                upk2(acc[3 * 8 + c2], lo3, hi3);
                int cA = col_off + 2 * c2;
                *(float4*)(Asm + cA * UAP + row_off) =
                    make_float4(eluf(lo0), eluf(lo1), eluf(lo2), eluf(lo3));
                *(float4*)(Asm + (cA + 1) * UAP + row_off) =
                    make_float4(eluf(hi0), eluf(hi1), eluf(hi2), eluf(hi3));
            }
#pragma unroll
            for (int q = 0; q < 32; q++) acc[q] = 0ull;
            CP_WAIT(0);
            __syncthreads();   // new A visible + chunk 4 ready
        } else if (s < 7) {
            CP_WAIT(0);
            __syncthreads();   // chunk s+1 ready; all warps done with buf (s&1)
        }
    }

    // ---- epilogue: score = sum_c elu(out[m][c]) * wlast[c] ----
    // sred overlays W0 (buf0): chunk 7 reads buf1 only, so no conflict.
    {
        float s0 = 0.f, s1 = 0.f, s2 = 0.f, s3 = 0.f;
#pragma unroll
        for (int c2 = 0; c2 < 8; c2++) {
            float wlo = wl[col_off + 2 * c2];
            float whi = wl[col_off + 2 * c2 + 1];
            float lo, hi;
            upk2(acc[0 * 8 + c2], lo, hi); s0 += eluf(lo) * wlo + eluf(hi) * whi;
            upk2(acc[1 * 8 + c2], lo, hi); s1 += eluf(lo) * wlo + eluf(hi) * whi;
            upk2(acc[2 * 8 + c2], lo, hi); s2 += eluf(lo) * wlo + eluf(hi) * whi;
            upk2(acc[3 * 8 + c2], lo, hi); s3 += eluf(lo) * wlo + eluf(hi) * whi;
        }
        float* sred = sm + U2_W0;
        sred[chunk * 132 + row_off + 0] = s0;
        sred[chunk * 132 + row_off + 1] = s1;
        sred[chunk * 132 + row_off + 2] = s2;
        sred[chunk * 132 + row_off + 3] = s3;
        __syncthreads();
        if (tid < 128) {
            float s = 0.f;
#pragma unroll
            for (int q = 0; q < 8; q++) s += sred[q * 132 + tid];
            g_scores[(size_t)pair * NROWS + r0 + tid] = s;
        }
    }
}

// ============================================================
// Kernel 5: softmax over n per (pair, b), accumulate & average.
// ============================================================
__global__ void __launch_bounds__(64) smax_kernel(float* __restrict__ out) {
    __shared__ float red[64];
    const int b   = blockIdx.x;
    const int tid = threadIdx.x;
    const bool act = tid < NPROD;
    float accv = 0.f;

    for (int pair = 0; pair < 9; pair++) {
        float s = act ? g_scores[(size_t)(pair * B_SZ + b) * NPROD + tid] : -1e30f;
        red[tid] = s;
        __syncthreads();
#pragma unroll
        for (int st = 32; st > 0; st >>= 1) {
            if (tid < st) red[tid] = fmaxf(red[tid], red[tid + st]);
            __syncthreads();
        }
        float mx = red[0];
        __syncthreads();
        float e = act ? expf(s - mx) : 0.f;
        red[tid] = e;
        __syncthreads();
#pragma unroll
        for (int st = 32; st > 0; st >>= 1) {
            if (tid < st) red[tid] += red[tid + st];
            __syncthreads();
        }
        float sum = red[0];
        __syncthreads();
        accv += 1e-6f + e / sum;
    }
    if (act)
        out[(size_t)b * NPROD + tid] = accv * (1.f / (1.f + 1e-6f * (float)NPROD)) / 9.f;
}

// ============================================================
extern "C" void kernel_launch(void* const* d_in, const int* in_sizes, int n_in,
                              void* d_out, int out_size) {
    const float* X     = (const float*)d_in[0];
    const float* Z     = (const float*)d_in[1];
    const float* Wx0   = (const float*)d_in[2];
    const float* Wx    = (const float*)d_in[3];
    const float* Wlx   = (const float*)d_in[4];
    const float* Wz0   = (const float*)d_in[5];
    const float* Wz    = (const float*)d_in[6];
    const float* Wlz   = (const float*)d_in[7];
    const float* Wu0   = (const float*)d_in[8];
    const float* Wu    = (const float*)d_in[9];
    const float* Wlast = (const float*)d_in[10];
    float* out = (float*)d_out;

    const size_t smemX = (size_t)X_SMEM_FLOATS * sizeof(float);  // 111360
    const size_t smemU = (size_t)U_SMEM_FLOATS * sizeof(float);  // 106048
    cudaFuncSetAttribute(x_kernel, cudaFuncAttributeMaxDynamicSharedMemorySize, (int)smemX);
    cudaFuncSetAttribute(u_kernel, cudaFuncAttributeMaxDynamicSharedMemorySize, (int)smemU);

    z_kernel<<<192, 128>>>(Z, Wz0, Wz, Wlz);
    d_kernel<<<dim3(32, 3), 256>>>(Z, Wu0);
    x_kernel<<<dim3(3200, 3), 256, smemX>>>(X, Wx0, Wx, Wlx, Wu0);
    u_kernel<<<28800, 256, smemU>>>(Wu, Wlast);
    smax_kernel<<<8192, 64>>>(out);
}

// round 17
// speedup vs baseline: 1.0264x; 1.0264x over previous
#include <cuda_runtime.h>
#include <cstdint>

typedef unsigned long long u64;

#define B_SZ   8192
#define NPROD  50
#define DXF    32
#define DZF    20
#define NROWS  (B_SZ * NPROD)       // 409600
#define WP128  140                  // 128-wide weight pitch (floats), remapped
#define UAP    132                  // u-kernel A-tile pitch (128 rows)
#define XAP    132                  // x-kernel A/H pitch (128 rows)

// ---------------- scratch (device globals, no allocation) ----------------
__device__ float g_Zj[3 * B_SZ * 16];                    // [KZ][B][16]
__device__ float g_D[3 * B_SZ * 128];                    // [KZ][B][128]
__device__ float g_E[(size_t)3 * 128 * NROWS];           // [KX][128][NROWS] column-major
__device__ float g_scores[9 * NROWS];                    // [pair][B][n]

// ---------------- packed f32x2 helpers ----------------
__device__ __forceinline__ u64 pk2(float lo, float hi) {
    u64 r; asm("mov.b64 %0, {%1, %2};" : "=l"(r) : "f"(lo), "f"(hi)); return r;
}
__device__ __forceinline__ void upk2(u64 v, float& lo, float& hi) {
    asm("mov.b64 {%0, %1}, %2;" : "=f"(lo), "=f"(hi) : "l"(v));
}
__device__ __forceinline__ void f2fma(u64& d, u64 a, u64 b) {
    asm("fma.rn.f32x2 %0, %1, %2, %0;" : "+l"(d) : "l"(a), "l"(b));
}
// fast elu: MUFU-based exp; abs err ~1e-6, fine vs 1e-3 threshold
__device__ __forceinline__ float eluf(float x) { return x > 0.f ? x : (__expf(x) - 1.f); }

__device__ __forceinline__ uint32_t smem_u32(const void* p) {
    uint32_t a;
    asm("{ .reg .u64 t; cvta.to.shared.u64 t, %1; cvt.u32.u64 %0, t; }" : "=r"(a) : "l"(p));
    return a;
}
__device__ __forceinline__ void cpasync16(uint32_t dst, const void* src) {
    asm volatile("cp.async.ca.shared.global [%0], [%1], 16;" :: "r"(dst), "l"(src) : "memory");
}
#define CP_COMMIT() asm volatile("cp.async.commit_group;" ::: "memory")
#define CP_WAIT(n)  asm volatile("cp.async.wait_group %0;" :: "n"(n) : "memory")

// Dense layer, register input/output, weights in shared. [IN][OUT] row-major.
template<int IN, int OUT, bool ELU>
__device__ __forceinline__ void dense_reg(const float (&in)[IN], const float* wsh, float (&out)[OUT]) {
    u64 acc[OUT / 2];
#pragma unroll
    for (int jj = 0; jj < OUT / 2; jj++) acc[jj] = 0ull;
#pragma unroll
    for (int k = 0; k < IN; k++) {
        u64 xk = pk2(in[k], in[k]);
        const ulonglong2* w = (const ulonglong2*)(wsh + k * OUT);
#pragma unroll
        for (int q = 0; q < OUT / 4; q++) {
            ulonglong2 ww = w[q];
            f2fma(acc[2 * q],     xk, ww.x);
            f2fma(acc[2 * q + 1], xk, ww.y);
        }
    }
#pragma unroll
    for (int jj = 0; jj < OUT / 2; jj++) {
        float lo, hi; upk2(acc[jj], lo, hi);
        out[2 * jj]     = ELU ? eluf(lo) : lo;
        out[2 * jj + 1] = ELU ? eluf(hi) : hi;
    }
}

template<int IN>
__device__ __forceinline__ void dense_half_reg(const float (&in)[IN], const float* wcol, u64 (&acc)[32]) {
#pragma unroll
    for (int q = 0; q < 32; q++) acc[q] = 0ull;
#pragma unroll
    for (int k = 0; k < IN; k++) {
        u64 uk = pk2(in[k], in[k]);
        const ulonglong2* w = (const ulonglong2*)(wcol + k * 128);
#pragma unroll
        for (int q = 0; q < 16; q++) {
            ulonglong2 ww = w[q];
            f2fma(acc[2 * q],     uk, ww.x);
            f2fma(acc[2 * q + 1], uk, ww.y);
        }
    }
}

// ============================================================
// Kernel 1: Z-branch.
// ============================================================
__global__ void __launch_bounds__(128) z_kernel(const float* __restrict__ Zin,
                                                const float* __restrict__ Wz0,
                                                const float* __restrict__ Wz,
                                                const float* __restrict__ Wlz) {
    __shared__ __align__(16) float w0[20 * 64];
    __shared__ __align__(16) float w1[64 * 64];
    __shared__ __align__(16) float w2[64 * 64];
    __shared__ __align__(16) float wl[64 * 16];
    const int j   = blockIdx.x >> 6;
    const int tid = threadIdx.x;
    const int b   = ((blockIdx.x & 63) << 7) + tid;

    {
        const float4* p0 = (const float4*)(Wz0 + j * 1280);
        const float4* p1 = (const float4*)(Wz  + j * 8192);
        const float4* p2 = (const float4*)(Wz  + j * 8192 + 4096);
        const float4* pl = (const float4*)(Wlz + j * 1024);
        for (int t = tid; t < 320;  t += 128) ((float4*)w0)[t] = p0[t];
        for (int t = tid; t < 1024; t += 128) ((float4*)w1)[t] = p1[t];
        for (int t = tid; t < 1024; t += 128) ((float4*)w2)[t] = p2[t];
        for (int t = tid; t < 256;  t += 128) ((float4*)wl)[t] = pl[t];
    }
    __syncthreads();

    float zv[20];
    const float4* zr = (const float4*)(Zin + (size_t)b * DZF);
#pragma unroll
    for (int t = 0; t < 5; t++) {
        float4 v = zr[t];
        zv[4 * t] = v.x; zv[4 * t + 1] = v.y; zv[4 * t + 2] = v.z; zv[4 * t + 3] = v.w;
    }

    float h1[64], h2[64], o[16];
    dense_reg<20, 64, true >(zv, w0, h1);
    dense_reg<64, 64, true >(h1, w1, h2);
    dense_reg<64, 64, true >(h2, w2, h1);
    dense_reg<64, 16, false>(h1, wl, o);

    float4* dst = (float4*)(g_Zj + (size_t)(j * B_SZ + b) * 16);
#pragma unroll
    for (int t = 0; t < 4; t++)
        dst[t] = make_float4(o[4 * t], o[4 * t + 1], o[4 * t + 2], o[4 * t + 3]);
}

// ============================================================
// Kernel 2: D_j[b][:] = Zj_j[b]·Wu0[48:64] + Z[b]·Wu0[64:84]
// ============================================================
__global__ void __launch_bounds__(256) d_kernel(const float* __restrict__ Zin,
                                                const float* __restrict__ Wu0) {
    __shared__ __align__(16) float w[36 * 128];
    const int j   = blockIdx.y;
    const int tid = threadIdx.x;
    const int b   = blockIdx.x * 256 + tid;

    const float4* src = (const float4*)(Wu0 + 48 * 128);
    for (int t = tid; t < 36 * 32; t += 256) ((float4*)w)[t] = src[t];
    __syncthreads();

    float in[36];
    const float4* zj = (const float4*)(g_Zj + (size_t)(j * B_SZ + b) * 16);
#pragma unroll
    for (int t = 0; t < 4; t++) {
        float4 v = zj[t];
        in[4 * t] = v.x; in[4 * t + 1] = v.y; in[4 * t + 2] = v.z; in[4 * t + 3] = v.w;
    }
    const float4* zr = (const float4*)(Zin + (size_t)b * DZF);
#pragma unroll
    for (int t = 0; t < 5; t++) {
        float4 v = zr[t];
        in[16 + 4 * t] = v.x; in[17 + 4 * t] = v.y; in[18 + 4 * t] = v.z; in[19 + 4 * t] = v.w;
    }

    float* dst = g_D + (size_t)(j * B_SZ + b) * 128;
    u64 acc[32];
#pragma unroll
    for (int half = 0; half < 2; half++) {
        dense_half_reg<36>(in, w + half * 64, acc);
        float4* d4 = (float4*)(dst + half * 64);
#pragma unroll
        for (int q = 0; q < 16; q++) {
            float a, bb, c, d;
            upk2(acc[2 * q], a, bb); upk2(acc[2 * q + 1], c, d);
            d4[q] = make_float4(a, bb, c, d);
        }
    }
}

// ============================================================
// Shared-weight staging with bank-group remaps (NON-OVERLAPPING).
// W68 (64-wide, pitch 68): off(ch) = ch*8 + ((ch>>2)&1)*4
// W140 (128-wide, pitch 140): off(ch) = ch*16 + (ch>>1)*4
// ============================================================
__device__ __forceinline__ void stage64(float* W68, const float* __restrict__ Wg,
                                        int Krows, int tid, int nthr) {
    for (int t = tid; t < Krows * 16; t += nthr) {
        int k = t >> 4, c4 = t & 15, ch = c4 >> 1, wi = c4 & 1;
        ((float4*)W68)[k * 17 + ch * 2 + ((ch >> 2) & 1) + wi] = ((const float4*)Wg)[t];
    }
}
__device__ __forceinline__ void stage128(float* W140, const float* __restrict__ Wg,
                                         int Krows, int tid, int nthr) {
    for (int t = tid; t < Krows * 32; t += nthr) {
        int k = t >> 5, c4 = t & 31, ch = c4 >> 2, wi = c4 & 3;
        ((float4*)W140)[k * 35 + ch * 4 + (ch >> 1) + wi] = ((const float4*)Wg)[t];
    }
}
__device__ __forceinline__ int wcol128(int chunk) {    // float offset of chunk base
    return chunk * 16 + (chunk >> 1) * 4;
}
// async: 32-k chunk (1024 src float4), remapped, one commit group (256 thr)
__device__ __forceinline__ void stage32_async(uint32_t dstbase, const float* __restrict__ Wg,
                                              int tid) {
#pragma unroll
    for (int it = 0; it < 4; it++) {
        int t = tid + it * 256;
        int k = t >> 5, c4 = t & 31, ch = c4 >> 2, wi = c4 & 3;
        cpasync16(dstbase + (uint32_t)(k * 35 + ch * 4 + (ch >> 1) + wi) * 16u,
                  (const float4*)Wg + t);
    }
    CP_COMMIT();
}

// 128-row x 64-col tile GEMM; micro 4 rows x 8 cols (rows paired). 256 thr.
template<int K, bool ELU>
__device__ __forceinline__ void gemm_tile64(const float* Ain, const float* W68, float* Aout,
                                            int row4, int tn8) {
    u64 acc[16];
#pragma unroll
    for (int q = 0; q < 16; q++) acc[q] = 0ull;
    const int wb = tn8 * 8 + ((tn8 >> 2) & 1) * 4;
#pragma unroll 4
    for (int k = 0; k < K; k++) {
        ulonglong2 ap = *(const ulonglong2*)(Ain + k * XAP + row4);
        const float4* wp = (const float4*)(W68 + k * 68 + wb);
        float4 b0 = wp[0], b1 = wp[1];
        u64 bd[8];
        bd[0] = pk2(b0.x, b0.x); bd[1] = pk2(b0.y, b0.y);
        bd[2] = pk2(b0.z, b0.z); bd[3] = pk2(b0.w, b0.w);
        bd[4] = pk2(b1.x, b1.x); bd[5] = pk2(b1.y, b1.y);
        bd[6] = pk2(b1.z, b1.z); bd[7] = pk2(b1.w, b1.w);
#pragma unroll
        for (int c = 0; c < 8; c++) {
            f2fma(acc[c],     ap.x, bd[c]);
            f2fma(acc[8 + c], ap.y, bd[c]);
        }
    }
#pragma unroll
    for (int c = 0; c < 8; c++) {
        float l0, h0, l1, h1;
        upk2(acc[c], l0, h0); upk2(acc[8 + c], l1, h1);
        if (ELU) { l0 = eluf(l0); h0 = eluf(h0); l1 = eluf(l1); h1 = eluf(h1); }
        *(float4*)(Aout + (tn8 * 8 + c) * XAP + row4) = make_float4(l0, h0, l1, h1);
    }
}

// ============================================================
// Kernel 3: X-branch, 128-row tiles, 256 threads, 2 blocks/SM.
// ============================================================
#define XO_AX 0
#define XO_H  (32 * XAP)              // 4224
#define XO_W  (XO_H + 128 * XAP)      // 21120
#define X_SMEM_FLOATS (XO_W + 6720)   // 27840 floats = 111360 B

__global__ void __launch_bounds__(256, 2) x_kernel(const float* __restrict__ Xin,
                                                   const float* __restrict__ Wx0,
                                                   const float* __restrict__ Wx,
                                                   const float* __restrict__ Wlx,
                                                   const float* __restrict__ Wu0) {
    extern __shared__ float xs[];
    float* AX = xs + XO_AX;
    float* H  = xs + XO_H;            // h1 = H, h2/LX = H + 64*XAP
    float* Wq = xs + XO_W;

    const int i   = blockIdx.y;
    const int tid = threadIdx.x;
    const int r0  = blockIdx.x * 128;

    const int row4 = (tid >> 3) * 4;          // 0..124 (32 groups)
    const int tn8  = tid & 7;

    const int rowE   = (tid & 31) * 4;        // 0..124
    const int chunkE = tid >> 5;              // 0..7
    const int wcolE  = wcol128(chunkE);
    const int col_offE = chunkE * 16;

    for (int t = tid; t < 1024; t += 256) {
        int m = t & 127, q = t >> 7;
        float4 v = *(const float4*)(Xin + (size_t)(r0 + m) * DXF + q * 4);
        AX[(q * 4 + 0) * XAP + m] = v.x; AX[(q * 4 + 1) * XAP + m] = v.y;
        AX[(q * 4 + 2) * XAP + m] = v.z; AX[(q * 4 + 3) * XAP + m] = v.w;
    }
    stage64(Wq, Wx0 + i * 2048, 32, tid, 256);
    __syncthreads();

    gemm_tile64<32, true>(AX, Wq, H, row4, tn8);                  // L1 -> h1
    __syncthreads();
    stage64(Wq, Wx + i * 8192, 64, tid, 256);
    __syncthreads();
    gemm_tile64<64, true>(H, Wq, H + 64 * XAP, row4, tn8);        // L2 -> h2
    __syncthreads();
    stage64(Wq, Wx + i * 8192 + 4096, 64, tid, 256);
    __syncthreads();
    gemm_tile64<64, true>(H + 64 * XAP, Wq, H, row4, tn8);        // L3 -> h1
    __syncthreads();
    for (int t = tid; t < 256; t += 256) {
        int k = t >> 2, c4 = t & 3;
        ((float4*)Wq)[k * 5 + c4] = ((const float4*)(Wlx + 2 * 1024))[t];  // Wlx[DX-1] (ref bug)
    }
    __syncthreads();
    {
        u64 acc[4];
#pragma unroll
        for (int q = 0; q < 4; q++) acc[q] = 0ull;
#pragma unroll 4
        for (int k = 0; k < 64; k++) {
            ulonglong2 ap = *(const ulonglong2*)(H + k * XAP + row4);
            float2 bw = *(const float2*)(Wq + k * 20 + tn8 * 2);
            u64 b0 = pk2(bw.x, bw.x), b1 = pk2(bw.y, bw.y);
            f2fma(acc[0], ap.x, b0); f2fma(acc[1], ap.x, b1);
            f2fma(acc[2], ap.y, b0); f2fma(acc[3], ap.y, b1);
        }
#pragma unroll
        for (int cc = 0; cc < 2; cc++) {
            float l0, h0, l1, h1;
            upk2(acc[cc], l0, h0); upk2(acc[2 + cc], l1, h1);
            *(float4*)(H + (64 + tn8 * 2 + cc) * XAP + row4) = make_float4(l0, h0, l1, h1);
        }
    }
    __syncthreads();
    stage128(Wq, Wu0, 48, tid, 256);
    __syncthreads();

    u64 acc[32];
    {
#pragma unroll
        for (int q = 0; q < 32; q++) acc[q] = 0ull;
#pragma unroll 4
        for (int k = 0; k < 48; k++) {
            const float* Ain = (k < 32) ? (AX + k * XAP) : (H + (64 + k - 32) * XAP);
            float4 av = *(const float4*)(Ain + rowE);
            const ulonglong2* bp = (const ulonglong2*)(Wq + k * WP128 + wcolE);
            ulonglong2 q0 = bp[0], q1 = bp[1], q2 = bp[2], q3 = bp[3];
            u64 bv[8] = {q0.x, q0.y, q1.x, q1.y, q2.x, q2.y, q3.x, q3.y};
            u64 av2[4];
            av2[0] = pk2(av.x, av.x); av2[1] = pk2(av.y, av.y);
            av2[2] = pk2(av.z, av.z); av2[3] = pk2(av.w, av.w);
#pragma unroll
            for (int r = 0; r < 4; r++)
#pragma unroll
                for (int c2 = 0; c2 < 8; c2++)
                    f2fma(acc[r * 8 + c2], av2[r], bv[c2]);
        }
    }
    __syncthreads();   // all LE reads of AX/LX done before overwriting H

#pragma unroll
    for (int c2 = 0; c2 < 8; c2++) {
        float lo0, hi0, lo1, hi1, lo2, hi2, lo3, hi3;
        upk2(acc[0 * 8 + c2], lo0, hi0);
        upk2(acc[1 * 8 + c2], lo1, hi1);
        upk2(acc[2 * 8 + c2], lo2, hi2);
        upk2(acc[3 * 8 + c2], lo3, hi3);
        int col = col_offE + 2 * c2;
        *(float4*)(H + col * XAP + rowE)       = make_float4(lo0, lo1, lo2, lo3);
        *(float4*)(H + (col + 1) * XAP + rowE) = make_float4(hi0, hi1, hi2, hi3);
    }
    __syncthreads();

    for (int t = tid; t < 4096; t += 256) {
        int c = t >> 5, q = t & 31;
        float4 v = *(const float4*)(H + c * XAP + q * 4);
        *(float4*)(g_E + ((size_t)i * 128 + c) * NROWS + r0 + q * 4) = v;
    }
}

// ============================================================
// Kernel 4: U-kernel (R15 distance-2 pipeline) + TILE-MAJOR block
// order: bx -> (tile, sub) so the 9 (i,j) blocks sharing a row tile
// are adjacent -> E/D row-blocks hit L2 for 2 of 3 uses.
// ============================================================
#define U2_A   0                          // 128 x 132 = 16896 floats
#define U2_W0  16896                      // 32 x 140 = 4480
#define U2_W1  (U2_W0 + 32 * WP128)       // 21376
#define U2_D   (U2_W1 + 32 * WP128)       // 25856 (4 x 132 = 528)
#define U2_WL  (U2_D + 528)               // 26384
#define U_SMEM_FLOATS (U2_WL + 128)       // 26512 floats = 106048 B

__device__ __forceinline__ void u_chunk32(const float* __restrict__ A0,
                                          const float* __restrict__ Wb,
                                          int row_off, int wcol, u64* acc) {
#pragma unroll 8
    for (int kk = 0; kk < 32; kk++) {
        float4 av = *(const float4*)(A0 + kk * UAP + row_off);
        const ulonglong2* bp = (const ulonglong2*)(Wb + kk * WP128 + wcol);
        ulonglong2 q0 = bp[0], q1 = bp[1], q2 = bp[2], q3 = bp[3];
        u64 bv[8] = {q0.x, q0.y, q1.x, q1.y, q2.x, q2.y, q3.x, q3.y};
        u64 av2[4];
        av2[0] = pk2(av.x, av.x); av2[1] = pk2(av.y, av.y);
        av2[2] = pk2(av.z, av.z); av2[3] = pk2(av.w, av.w);
#pragma unroll
        for (int r = 0; r < 4; r++)
#pragma unroll
            for (int c2 = 0; c2 < 8; c2++)
                f2fma(acc[r * 8 + c2], av2[r], bv[c2]);
    }
}

__global__ void __launch_bounds__(256, 2) u_kernel(const float* __restrict__ Wu,
                                                   const float* __restrict__ Wlast) {
    extern __shared__ float sm[];
    float* Asm = sm + U2_A;
    float* Dsh = sm + U2_D;
    float* wl  = sm + U2_WL;
    const uint32_t w0u = smem_u32(sm + U2_W0);
    const uint32_t w1u = smem_u32(sm + U2_W1);

    const int tid  = threadIdx.x;
    const int bx   = blockIdx.x;             // 0..28799
    const int tile = bx / 9;                 // 0..3199 (row tile)
    const int sub  = bx - tile * 9;          // 0..8 (pair)
    const int pair = sub;
    const int r0   = tile * 128;
    const int i    = sub / 3;
    const int j    = sub - 3 * i;
    const int b0   = r0 / NPROD;

    const int wid    = tid >> 5;              // 0..7
    const int warp_c = wid & 1;
    const int warp_r = wid >> 1;               // 0..3
    const int lane   = tid & 31;
    const int lr     = lane & 7;
    const int lc     = lane >> 3;
    const int row_off = warp_r * 32 + lr * 4;   // 0..124
    const int chunk   = warp_c * 4 + lc;        // 0..7
    const int wcol    = wcol128(chunk);
    const int col_off = chunk * 16;

    // ---- stage D + wlast; prefetch W chunks 0,1 ----
    for (int t = tid; t < 512; t += 256) {
        int bl = t >> 7, k = t & 127;
        int bb = b0 + bl;
        if (bb < B_SZ) Dsh[bl * 132 + k] = g_D[((size_t)j * B_SZ + bb) * 128 + k];
    }
    if (tid < 128) wl[tid] = Wlast[tid];
    stage32_async(w0u, Wu, tid);                 // chunk 0 (l0 k0-31)
    stage32_async(w1u, Wu + 4096, tid);          // chunk 1 (l0 k32-63)
    __syncthreads();   // Dsh visible

    // ---- prologue: A[k][m] = elu(E + D) (overlaps cp.async) ----
    {
        const float* Eb = g_E + (size_t)i * 128 * NROWS + r0;
#pragma unroll 4
        for (int it = 0; it < 16; it++) {
            int v = tid + it * 256;
            int k = v >> 5;
            int m = (v & 31) * 4;
            float4 e = *(const float4*)(Eb + (size_t)k * NROWS + m);
            int rg = r0 + m;
            float o0 = eluf(e.x + Dsh[((rg    ) / NPROD - b0) * 132 + k]);
            float o1 = eluf(e.y + Dsh[((rg + 1) / NPROD - b0) * 132 + k]);
            float o2 = eluf(e.z + Dsh[((rg + 2) / NPROD - b0) * 132 + k]);
            float o3 = eluf(e.w + Dsh[((rg + 3) / NPROD - b0) * 132 + k]);
            *(float4*)(Asm + k * UAP + m) = make_float4(o0, o1, o2, o3);
        }
    }

    u64 acc[32];
#pragma unroll
    for (int q = 0; q < 32; q++) acc[q] = 0ull;

    // ---- 8 chunks (distance-2 pipeline): l0c0..l0c3, l1c0..l1c3 ----
#pragma unroll 1
    for (int s = 0; s < 8; s++) {
        if (s < 7) { CP_WAIT(1); } else { CP_WAIT(0); }
        __syncthreads();   // chunk s ready; A/transition writes visible
        u_chunk32(Asm + (s & 3) * 32 * UAP, sm + ((s & 1) ? U2_W1 : U2_W0),
                  row_off, wcol, acc);
        __syncthreads();   // all warps done with this W buffer (and A, if layer end)

        if (s == 3) {
            // transition: A[col][m] = elu(out[m][col]); reset acc
#pragma unroll
            for (int c2 = 0; c2 < 8; c2++) {
                float lo0, hi0, lo1, hi1, lo2, hi2, lo3, hi3;
                upk2(acc[0 * 8 + c2], lo0, hi0);
                upk2(acc[1 * 8 + c2], lo1, hi1);
                upk2(acc[2 * 8 + c2], lo2, hi2);
                upk2(acc[3 * 8 + c2], lo3, hi3);
                int cA = col_off + 2 * c2;
                *(float4*)(Asm + cA * UAP + row_off) =
                    make_float4(eluf(lo0), eluf(lo1), eluf(lo2), eluf(lo3));
                *(float4*)(Asm + (cA + 1) * UAP + row_off) =
                    make_float4(eluf(hi0), eluf(hi1), eluf(hi2), eluf(hi3));
            }
#pragma unroll
            for (int q = 0; q < 32; q++) acc[q] = 0ull;
        }
        if (s < 6) stage32_async((s & 1) ? w1u : w0u, Wu + (s + 2) * 4096, tid);
    }

    // ---- epilogue: score = sum_c elu(out[m][c]) * wlast[c] ----
    {
        float s0 = 0.f, s1 = 0.f, s2 = 0.f, s3 = 0.f;
#pragma unroll
        for (int c2 = 0; c2 < 8; c2++) {
            float wlo = wl[col_off + 2 * c2];
            float whi = wl[col_off + 2 * c2 + 1];
            float lo, hi;
            upk2(acc[0 * 8 + c2], lo, hi); s0 += eluf(lo) * wlo + eluf(hi) * whi;
            upk2(acc[1 * 8 + c2], lo, hi); s1 += eluf(lo) * wlo + eluf(hi) * whi;
            upk2(acc[2 * 8 + c2], lo, hi); s2 += eluf(lo) * wlo + eluf(hi) * whi;
            upk2(acc[3 * 8 + c2], lo, hi); s3 += eluf(lo) * wlo + eluf(hi) * whi;
        }
        // partial reduction in W0 area (all W reads done; last sync above)
        float* sred = sm + U2_W0;
        sred[chunk * 132 + row_off + 0] = s0;
        sred[chunk * 132 + row_off + 1] = s1;
        sred[chunk * 132 + row_off + 2] = s2;
        sred[chunk * 132 + row_off + 3] = s3;
        __syncthreads();
        if (tid < 128) {
            float s = 0.f;
#pragma unroll
            for (int q = 0; q < 8; q++) s += sred[q * 132 + tid];
            g_scores[(size_t)pair * NROWS + r0 + tid] = s;
        }
    }
}

// ============================================================
// Kernel 5: softmax over n per (pair, b), accumulate & average.
// ============================================================
__global__ void __launch_bounds__(64) smax_kernel(float* __restrict__ out) {
    __shared__ float red[64];
    const int b   = blockIdx.x;
    const int tid = threadIdx.x;
    const bool act = tid < NPROD;
    float accv = 0.f;

    for (int pair = 0; pair < 9; pair++) {
        float s = act ? g_scores[(size_t)(pair * B_SZ + b) * NPROD + tid] : -1e30f;
        red[tid] = s;
        __syncthreads();
#pragma unroll
        for (int st = 32; st > 0; st >>= 1) {
            if (tid < st) red[tid] = fmaxf(red[tid], red[tid + st]);
            __syncthreads();
        }
        float mx = red[0];
        __syncthreads();
        float e = act ? expf(s - mx) : 0.f;
        red[tid] = e;
        __syncthreads();
#pragma unroll
        for (int st = 32; st > 0; st >>= 1) {
            if (tid < st) red[tid] += red[tid + st];
            __syncthreads();
        }
        float sum = red[0];
        __syncthreads();
        accv += 1e-6f + e / sum;
    }
    if (act)
        out[(size_t)b * NPROD + tid] = accv * (1.f / (1.f + 1e-6f * (float)NPROD)) / 9.f;
}

// ============================================================
extern "C" void kernel_launch(void* const* d_in, const int* in_sizes, int n_in,
                              void* d_out, int out_size) {
    const float* X     = (const float*)d_in[0];
    const float* Z     = (const float*)d_in[1];
    const float* Wx0   = (const float*)d_in[2];
    const float* Wx    = (const float*)d_in[3];
    const float* Wlx   = (const float*)d_in[4];
    const float* Wz0   = (const float*)d_in[5];
    const float* Wz    = (const float*)d_in[6];
    const float* Wlz   = (const float*)d_in[7];
    const float* Wu0   = (const float*)d_in[8];
    const float* Wu    = (const float*)d_in[9];
    const float* Wlast = (const float*)d_in[10];
    float* out = (float*)d_out;

    const size_t smemX = (size_t)X_SMEM_FLOATS * sizeof(float);  // 111360
    const size_t smemU = (size_t)U_SMEM_FLOATS * sizeof(float);  // 106048
    cudaFuncSetAttribute(x_kernel, cudaFuncAttributeMaxDynamicSharedMemorySize, (int)smemX);
    cudaFuncSetAttribute(u_kernel, cudaFuncAttributeMaxDynamicSharedMemorySize, (int)smemU);

    z_kernel<<<192, 128>>>(Z, Wz0, Wz, Wlz);
    d_kernel<<<dim3(32, 3), 256>>>(Z, Wu0);
    x_kernel<<<dim3(3200, 3), 256, smemX>>>(X, Wx0, Wx, Wlx, Wu0);
    u_kernel<<<28800, 256, smemU>>>(Wu, Wlast);
    smax_kernel<<<8192, 64>>>(out);
}